// round 3
// baseline (speedup 1.0000x reference)
#include <cuda_runtime.h>

#define B_TOTAL 32768
#define F_TOTAL 200
#define D_IN    5
#define H_DIM   15
#define OUT_DIM 30
#define OPAD    32
#define FSPLIT  5
#define FCHUNK  (F_TOTAL / FSPLIT)   // 40
#define FSUB    10                   // features per y sub-tile
#define NSUB    (FCHUNK / FSUB)      // 4
#define TPB     128
#define ROWS_PER_CTA 256             // R=2 rows per thread
#define YCOLS   (FSUB * D_IN)        // 50
#define YSTRIDE 51                   // padded: gcd(51,32)=1 -> conflict-free

// smem layout (floats): sW 6400 | sB 1280 | sC 1280 | sY 256*51=13056  => 88064 B
#define SM_W 0
#define SM_B (FCHUNK * D_IN * OPAD)          // 6400
#define SM_C (SM_B + FCHUNK * OPAD)          // 7680
#define SM_Y (SM_C + FCHUNK * OPAD)          // 8960
#define SM_TOTAL ((SM_Y + ROWS_PER_CTA * YSTRIDE) * 4)

// Scratch (allocation-free rule: __device__ globals)
__device__ __align__(16) float g_W12[F_TOTAL * D_IN * OPAD];
__device__ __align__(16) float g_b12[F_TOTAL * OPAD];
__device__ __align__(16) float g_W3p[F_TOTAL * OPAD];
__device__ __align__(16) float g_partial[FSPLIT][B_TOTAL];

// ---- packed f32x2 helpers ----
static __device__ __forceinline__ unsigned long long pk2(float x, float y) {
    unsigned long long r;
    asm("mov.b64 %0, {%1, %2};" : "=l"(r)
        : "r"(__float_as_uint(x)), "r"(__float_as_uint(y)));
    return r;
}
static __device__ __forceinline__ void upk2(unsigned long long v, float& x, float& y) {
    unsigned a, b;
    asm("mov.b64 {%0, %1}, %2;" : "=r"(a), "=r"(b) : "l"(v));
    x = __uint_as_float(a); y = __uint_as_float(b);
}
static __device__ __forceinline__ unsigned long long ffma2(
    unsigned long long a, unsigned long long b, unsigned long long c) {
    unsigned long long d;
    asm("fma.rn.f32x2 %0, %1, %2, %3;" : "=l"(d) : "l"(a), "l"(b), "l"(c));
    return d;
}
static __device__ __forceinline__ unsigned long long relu2(unsigned long long v) {
    float a, b;
    upk2(v, a, b);
    return pk2(fmaxf(a, 0.f), fmaxf(b, 0.f));
}

// ---- Kernel 1: fold W1@W2 (no ReLU between layers!), flattened for occupancy ----
// idx < 32000: one (f,i,o) element of W12. idx in [32000,38400): one (f,o) of b12/W3p.
__global__ void prep_kernel(const float* __restrict__ W1, const float* __restrict__ b1,
                            const float* __restrict__ W2, const float* __restrict__ b2,
                            const float* __restrict__ W3) {
    const int idx = blockIdx.x * blockDim.x + threadIdx.x;
    if (idx < F_TOTAL * D_IN * OPAD) {
        const int f = idx / (D_IN * OPAD);
        const int rem = idx - f * (D_IN * OPAD);
        const int i = rem >> 5, o = rem & 31;
        const float* w1 = W1 + (f * D_IN + i) * H_DIM;
        const float* w2 = W2 + f * H_DIM * OUT_DIM + o;
        float s = 0.f;
        if (o < OUT_DIM) {
            #pragma unroll
            for (int h = 0; h < H_DIM; ++h) s += w1[h] * w2[h * OUT_DIM];
        }
        g_W12[idx] = s;
    } else if (idx < F_TOTAL * D_IN * OPAD + F_TOTAL * OPAD) {
        const int k = idx - F_TOTAL * D_IN * OPAD;
        const int f = k >> 5, o = k & 31;
        float sb = 0.f, w3v = 0.f;
        if (o < OUT_DIM) {
            const float* w2 = W2 + f * H_DIM * OUT_DIM + o;
            #pragma unroll
            for (int h = 0; h < H_DIM; ++h) sb += b1[f * H_DIM + h] * w2[h * OUT_DIM];
            sb += b2[f * OUT_DIM + o];
            w3v = W3[f * OUT_DIM + o];
        }
        g_b12[k] = sb;
        g_W3p[k] = w3v;
    }
}

// ---- Kernel 2: main fused MLP with coalesced y staging ----
__global__ __launch_bounds__(TPB) void main_kernel(const float* __restrict__ y) {
    extern __shared__ __align__(16) float smem[];
    float* sW = smem + SM_W;
    float* sB = smem + SM_B;
    float* sC = smem + SM_C;
    float* sY = smem + SM_Y;

    const int tid  = threadIdx.x;
    const int lane = tid & 31;
    const int wrp  = tid >> 5;
    const int fbase = blockIdx.y * FCHUNK;
    const int b0 = blockIdx.x * ROWS_PER_CTA;

    // cooperative weight fill (float4)
    {
        const float4* gw = (const float4*)(g_W12 + fbase * D_IN * OPAD);
        float4* sw4 = (float4*)sW;
        #pragma unroll 4
        for (int t = tid; t < FCHUNK * D_IN * OPAD / 4; t += TPB) sw4[t] = gw[t];
        const float4* gb = (const float4*)(g_b12 + fbase * OPAD);
        const float4* gc = (const float4*)(g_W3p + fbase * OPAD);
        float4* sb4 = (float4*)sB;
        float4* sc4 = (float4*)sC;
        #pragma unroll
        for (int t = tid; t < FCHUNK * OPAD / 4; t += TPB) {
            sb4[t] = gb[t];
            sc4[t] = gc[t];
        }
    }

    unsigned long long accA0 = 0ull, accB0 = 0ull;  // row tid
    unsigned long long accA1 = 0ull, accB1 = 0ull;  // row tid+128

    for (int s = 0; s < NSUB; ++s) {
        __syncthreads();   // previous sub-tile consumed (covers weight fill at s=0)
        // coalesced y sub-tile load: 256 rows x 50 contiguous floats each
        for (int r = wrp; r < ROWS_PER_CTA; r += TPB / 32) {
            const float* src = y + (size_t)(b0 + r) * (F_TOTAL * D_IN)
                                 + (fbase + s * FSUB) * D_IN;
            float* dst = sY + r * YSTRIDE;
            for (int c = lane; c < YCOLS; c += 32) dst[c] = src[c];
        }
        __syncthreads();

        const float* yr0 = sY + tid * YSTRIDE;
        const float* yr1 = sY + (tid + TPB) * YSTRIDE;

        #pragma unroll 1
        for (int ff = 0; ff < FSUB; ++ff) {
            const int f = s * FSUB + ff;
            unsigned long long yp0[D_IN], yp1[D_IN];
            #pragma unroll
            for (int i = 0; i < D_IN; ++i) {
                float v0 = yr0[ff * D_IN + i];
                float v1 = yr1[ff * D_IN + i];
                yp0[i] = pk2(v0, v0);
                yp1[i] = pk2(v1, v1);
            }
            const ulonglong2* wp = (const ulonglong2*)(sW + f * D_IN * OPAD);
            const ulonglong2* bp = (const ulonglong2*)(sB + f * OPAD);
            const ulonglong2* cp = (const ulonglong2*)(sC + f * OPAD);

            #pragma unroll
            for (int j = 0; j < OPAD / 4; ++j) {
                ulonglong2 bb = bp[j];
                ulonglong2 t0 = bb, t1 = bb;
                #pragma unroll
                for (int i = 0; i < D_IN; ++i) {
                    ulonglong2 w = wp[i * (OPAD / 4) + j];  // broadcast LDS.128
                    t0.x = ffma2(yp0[i], w.x, t0.x);
                    t0.y = ffma2(yp0[i], w.y, t0.y);
                    t1.x = ffma2(yp1[i], w.x, t1.x);
                    t1.y = ffma2(yp1[i], w.y, t1.y);
                }
                ulonglong2 c = cp[j];
                accA0 = ffma2(relu2(t0.x), c.x, accA0);
                accB0 = ffma2(relu2(t0.y), c.y, accB0);
                accA1 = ffma2(relu2(t1.x), c.x, accA1);
                accB1 = ffma2(relu2(t1.y), c.y, accB1);
            }
        }
    }

    float r0, r1, r2, r3;
    upk2(accA0, r0, r1); upk2(accB0, r2, r3);
    g_partial[blockIdx.y][b0 + tid] = (r0 + r1) + (r2 + r3);
    upk2(accA1, r0, r1); upk2(accB1, r2, r3);
    g_partial[blockIdx.y][b0 + tid + TPB] = (r0 + r1) + (r2 + r3);
}

// ---- Kernel 3: deterministic reduce ----
__global__ void reduce_kernel(float* __restrict__ out, const float* __restrict__ b3) {
    const int i = blockIdx.x * blockDim.x + threadIdx.x;
    float s = ((g_partial[0][i] + g_partial[1][i]) +
               (g_partial[2][i] + g_partial[3][i])) + g_partial[4][i];
    out[i] = s + b3[0];
}

extern "C" void kernel_launch(void* const* d_in, const int* in_sizes, int n_in,
                              void* d_out, int out_size) {
    const float* y  = (const float*)d_in[0];
    const float* W1 = (const float*)d_in[1];
    const float* b1 = (const float*)d_in[2];
    const float* W2 = (const float*)d_in[3];
    const float* b2 = (const float*)d_in[4];
    const float* W3 = (const float*)d_in[5];
    const float* b3 = (const float*)d_in[6];
    float* out = (float*)d_out;

    cudaFuncSetAttribute(main_kernel,
                         cudaFuncAttributeMaxDynamicSharedMemorySize, SM_TOTAL);

    {   // prep: 38400 work items
        const int total = F_TOTAL * D_IN * OPAD + F_TOTAL * OPAD;
        prep_kernel<<<(total + 255) / 256, 256>>>(W1, b1, W2, b2, W3);
    }

    dim3 grid(B_TOTAL / ROWS_PER_CTA, FSPLIT);   // 128 x 5
    main_kernel<<<grid, TPB, SM_TOTAL>>>(y);

    reduce_kernel<<<B_TOTAL / 256, 256>>>(out, b3);
}

// round 4
// speedup vs baseline: 5.8047x; 5.8047x over previous
#include <cuda_runtime.h>

#define B_TOTAL 32768
#define F_TOTAL 200
#define D_IN    5
#define H_DIM   15
#define OUT_DIM 30
#define OPAD    32
#define FSPLIT  8
#define FCHUNK  (F_TOTAL / FSPLIT)   // 25
#define FSUB    5                    // features per y sub-tile
#define NSUB    (FCHUNK / FSUB)      // 5
#define TPB     256
#define ROWS_PER_CTA 256             // 1 row per thread
#define YCOLS   (FSUB * D_IN)        // 25
#define YSTRIDE 27                   // odd -> conflict-free per-lane reads

// smem layout (floats)
#define SM_W 0
#define SM_B (FCHUNK * D_IN * OPAD)            // 4000
#define SM_C (SM_B + FCHUNK * OPAD)            // 4800
#define SM_Y (SM_C + FCHUNK * OPAD)            // 5600
#define SM_TOTAL ((SM_Y + ROWS_PER_CTA * YSTRIDE) * 4)   // 50048 B -> 4 CTAs/SM

// Scratch (allocation-free rule: __device__ globals)
__device__ __align__(16) float g_W12[F_TOTAL * D_IN * OPAD];
__device__ __align__(16) float g_b12[F_TOTAL * OPAD];
__device__ __align__(16) float g_W3p[F_TOTAL * OPAD];
__device__ __align__(16) float g_partial[FSPLIT][B_TOTAL];

// ---- packed f32x2 helpers ----
static __device__ __forceinline__ unsigned long long pk2(float x, float y) {
    unsigned long long r;
    asm("mov.b64 %0, {%1, %2};" : "=l"(r)
        : "r"(__float_as_uint(x)), "r"(__float_as_uint(y)));
    return r;
}
static __device__ __forceinline__ void upk2(unsigned long long v, float& x, float& y) {
    unsigned a, b;
    asm("mov.b64 {%0, %1}, %2;" : "=r"(a), "=r"(b) : "l"(v));
    x = __uint_as_float(a); y = __uint_as_float(b);
}
static __device__ __forceinline__ unsigned long long ffma2(
    unsigned long long a, unsigned long long b, unsigned long long c) {
    unsigned long long d;
    asm("fma.rn.f32x2 %0, %1, %2, %3;" : "=l"(d) : "l"(a), "l"(b), "l"(c));
    return d;
}
static __device__ __forceinline__ unsigned long long relu2(unsigned long long v) {
    float a, b;
    upk2(v, a, b);
    return pk2(fmaxf(a, 0.f), fmaxf(b, 0.f));
}

// ---- Kernel 1: fold W1@W2 (no ReLU between the two linears) ----
__global__ void prep_kernel(const float* __restrict__ W1, const float* __restrict__ b1,
                            const float* __restrict__ W2, const float* __restrict__ b2,
                            const float* __restrict__ W3) {
    const int idx = blockIdx.x * blockDim.x + threadIdx.x;
    if (idx < F_TOTAL * D_IN * OPAD) {
        const int f = idx / (D_IN * OPAD);
        const int rem = idx - f * (D_IN * OPAD);
        const int i = rem >> 5, o = rem & 31;
        const float* w1 = W1 + (f * D_IN + i) * H_DIM;
        const float* w2 = W2 + f * H_DIM * OUT_DIM + o;
        float s = 0.f;
        if (o < OUT_DIM) {
            #pragma unroll
            for (int h = 0; h < H_DIM; ++h) s += w1[h] * w2[h * OUT_DIM];
        }
        g_W12[idx] = s;
    } else if (idx < F_TOTAL * D_IN * OPAD + F_TOTAL * OPAD) {
        const int k = idx - F_TOTAL * D_IN * OPAD;
        const int f = k >> 5, o = k & 31;
        float sb = 0.f, w3v = 0.f;
        if (o < OUT_DIM) {
            const float* w2 = W2 + f * H_DIM * OUT_DIM + o;
            #pragma unroll
            for (int h = 0; h < H_DIM; ++h) sb += b1[f * H_DIM + h] * w2[h * OUT_DIM];
            sb += b2[f * OUT_DIM + o];
            w3v = W3[f * OUT_DIM + o];
        }
        g_b12[k] = sb;
        g_W3p[k] = w3v;
    }
}

// ---- Kernel 2: main fused MLP, coalesced y staging, 32 warps/SM ----
__global__ __launch_bounds__(TPB) void main_kernel(const float* __restrict__ y) {
    extern __shared__ __align__(16) float smem[];
    float* sW = smem + SM_W;
    float* sB = smem + SM_B;
    float* sC = smem + SM_C;
    float* sY = smem + SM_Y;

    const int tid  = threadIdx.x;
    const int lane = tid & 31;
    const int wrp  = tid >> 5;
    const int fbase = blockIdx.y * FCHUNK;
    const int b0 = blockIdx.x * ROWS_PER_CTA;

    // cooperative weight fill (float4, broadcast-friendly layout)
    {
        const float4* gw = (const float4*)(g_W12 + fbase * D_IN * OPAD);
        float4* sw4 = (float4*)sW;
        #pragma unroll
        for (int t = tid; t < FCHUNK * D_IN * OPAD / 4; t += TPB) sw4[t] = gw[t];
        const float4* gb = (const float4*)(g_b12 + fbase * OPAD);
        const float4* gc = (const float4*)(g_W3p + fbase * OPAD);
        float4* sb4 = (float4*)sB;
        float4* sc4 = (float4*)sC;
        if (tid < FCHUNK * OPAD / 4) {
            sb4[tid] = gb[tid];
            sc4[tid] = gc[tid];
        }
    }

    unsigned long long accA = 0ull, accB = 0ull;

    for (int s = 0; s < NSUB; ++s) {
        __syncthreads();   // previous tile consumed (also covers weight fill at s=0)
        // coalesced y sub-tile: 256 rows x 25 contiguous floats
        {
            const float* srcb = y + (size_t)b0 * (F_TOTAL * D_IN)
                                  + (fbase + s * FSUB) * D_IN;
            #pragma unroll 4
            for (int r = wrp; r < ROWS_PER_CTA; r += TPB / 32) {
                if (lane < YCOLS)
                    sY[r * YSTRIDE + lane] = srcb[(size_t)r * (F_TOTAL * D_IN) + lane];
            }
        }
        __syncthreads();

        const float* yr = sY + tid * YSTRIDE;

        #pragma unroll
        for (int ff = 0; ff < FSUB; ++ff) {
            const int f = s * FSUB + ff;
            unsigned long long yp[D_IN];
            #pragma unroll
            for (int i = 0; i < D_IN; ++i) {
                float v = yr[ff * D_IN + i];
                yp[i] = pk2(v, v);
            }
            const ulonglong2* wp = (const ulonglong2*)(sW + f * D_IN * OPAD);
            const ulonglong2* bp = (const ulonglong2*)(sB + f * OPAD);
            const ulonglong2* cp = (const ulonglong2*)(sC + f * OPAD);

            #pragma unroll
            for (int j = 0; j < OPAD / 4; ++j) {
                ulonglong2 t = bp[j];
                #pragma unroll
                for (int i = 0; i < D_IN; ++i) {
                    ulonglong2 w = wp[i * (OPAD / 4) + j];   // broadcast LDS.128
                    t.x = ffma2(yp[i], w.x, t.x);
                    t.y = ffma2(yp[i], w.y, t.y);
                }
                ulonglong2 c = cp[j];
                accA = ffma2(relu2(t.x), c.x, accA);
                accB = ffma2(relu2(t.y), c.y, accB);
            }
        }
    }

    float r0, r1, r2, r3;
    upk2(accA, r0, r1); upk2(accB, r2, r3);
    g_partial[blockIdx.y][b0 + tid] = (r0 + r1) + (r2 + r3);
}

// ---- Kernel 3: deterministic reduce ----
__global__ void reduce_kernel(float* __restrict__ out, const float* __restrict__ b3) {
    const int i = blockIdx.x * blockDim.x + threadIdx.x;
    float s = ((g_partial[0][i] + g_partial[1][i]) +
               (g_partial[2][i] + g_partial[3][i])) +
              ((g_partial[4][i] + g_partial[5][i]) +
               (g_partial[6][i] + g_partial[7][i]));
    out[i] = s + b3[0];
}

// no-op: pads the launch count so ncu's "-s 5 -c 1" (6th launch) hits main_kernel
__global__ void nudge_kernel() {}

extern "C" void kernel_launch(void* const* d_in, const int* in_sizes, int n_in,
                              void* d_out, int out_size) {
    const float* y  = (const float*)d_in[0];
    const float* W1 = (const float*)d_in[1];
    const float* b1 = (const float*)d_in[2];
    const float* W2 = (const float*)d_in[3];
    const float* b2 = (const float*)d_in[4];
    const float* W3 = (const float*)d_in[5];
    const float* b3 = (const float*)d_in[6];
    float* out = (float*)d_out;

    cudaFuncSetAttribute(main_kernel,
                         cudaFuncAttributeMaxDynamicSharedMemorySize, SM_TOTAL);

    {   // prep: 38400 work items
        const int total = F_TOTAL * D_IN * OPAD + F_TOTAL * OPAD;
        prep_kernel<<<(total + 255) / 256, 256>>>(W1, b1, W2, b2, W3);
    }

    dim3 grid(B_TOTAL / ROWS_PER_CTA, FSPLIT);   // 128 x 8
    main_kernel<<<grid, TPB, SM_TOTAL>>>(y);

    reduce_kernel<<<B_TOTAL / 256, 256>>>(out, b3);

    nudge_kernel<<<1, 1>>>();
}